// round 15
// baseline (speedup 1.0000x reference)
#include <cuda_runtime.h>
#include <cuda_fp16.h>
#include <cstdint>
#include <math.h>

// Problem constants
#define BATCH   16
#define DIM     512
#define SEQL    4096
#define NFFT    1024
#define HOP     256
#define FBINS   513          // NFFT/2 + 1
#define NCOL    65536        // BATCH * SEQL
#define OUTPER  1048576      // SEQL * HOP
#define PAD     384          // (NFFT - HOP)/2
#define TWO_PI  6.283185307179586476925286766559f

// spec_T K layout: [Re: 0..512][pad][Im: 544..1056][pad]
#define KR      544
#define KTOT    1088

// GEMM1 covers bins 0..511 (8 mblocks); bin 512 handled by nyq_kernel.
#define NMBLK   8

// GEMM1 tiling: block 128x256, 512 threads, warp tile 64x32 (2x8 grid), fp16 mma
#define BM 128
#define BN 256
#define BK 32
#define NTHR 512
#define A_HALVES 4096
#define B_HALVES 8192
#define A_BYTES  (A_HALVES * 2)  // 8192
#define B_BYTES  (B_HALVES * 2)  // 16384
#define STAGE_BYTES (A_BYTES + B_BYTES)   // 24576
#define SMEM_BYTES 69632          // max(2*STAGE_BYTES=49152, Tt=128*136*4=69632)

// Fused iFFT+OLA: hops per block, dual-frame (two 256-thread groups)
#define HOPB 32
#define OLA_SMEM (8192 * 4 + 6 * 1024 * 4)   // bufs 32KB + ring 24KB = 57344

// ---------------------------------------------------------------------------
// Scratch (static device globals)
// ---------------------------------------------------------------------------
__device__ float  g_specT[(size_t)NCOL * KTOT];       // spec m-major [m][k], fp32
__device__ __half g_xB[(size_t)BATCH * DIM * SEQL];   // x, fragment-major fp16
__device__ __half g_Wp[(size_t)16 * NMBLK * A_HALVES];// W, fragment-major fp16
__device__ float2 g_tw[1024];                         // exp(+2*pi*i*a/1024)
__device__ float  g_winS[NFFT];                       // hann[n] / 1024
__device__ float  g_invenv[OUTPER];                   // 1 / window-square envelope

__device__ __forceinline__ void mma_f16(float c[4], const uint32_t a[4], const uint32_t b[2]) {
    asm volatile(
        "mma.sync.aligned.m16n8k16.row.col.f32.f16.f16.f32 "
        "{%0,%1,%2,%3}, {%4,%5,%6,%7}, {%8,%9}, {%0,%1,%2,%3};\n"
        : "+f"(c[0]), "+f"(c[1]), "+f"(c[2]), "+f"(c[3])
        : "r"(a[0]), "r"(a[1]), "r"(a[2]), "r"(a[3]), "r"(b[0]), "r"(b[1]));
}

#define CP_ASYNC_CG(dst_u32, src_ptr) \
    asm volatile("cp.async.cg.shared.global [%0], [%1], 16;\n" \
                 :: "r"(dst_u32), "l"(src_ptr))
#define CP_COMMIT() asm volatile("cp.async.commit_group;\n")
#define CP_WAIT1()  asm volatile("cp.async.wait_group 1;\n")
#define CP_WAIT0()  asm volatile("cp.async.wait_group 0;\n")

// Named barrier for a 256-thread group (warp-aligned split)
#define BAR_GRP(id) asm volatile("bar.sync %0, 256;" :: "r"(id) : "memory")

// ---------------------------------------------------------------------------
// Prep kernels
// ---------------------------------------------------------------------------
__global__ void gen_tables_kernel() {
    int i = blockIdx.x * blockDim.x + threadIdx.x;
    if (i < 1024) {
        float s, c;
        sincosf(TWO_PI * (float)i * (1.0f / 1024.0f), &s, &c);
        g_tw[i] = make_float2(c, s);
        float w = 0.5f * (1.0f - c);      // hann[i]
        g_winS[i] = w * (1.0f / 1024.0f);
    }
}

// Precompute 1/env(t): env = sum over valid frames of hann^2 (batch-independent).
__global__ void gen_invenv_kernel() {
    int t = blockIdx.x * blockDim.x + threadIdx.x;
    if (t >= OUTPER) return;
    int g = t + PAD;
    int lmin = (g - (NFFT - 1) + (HOP - 1)) >> 8;
    if (lmin < 0) lmin = 0;
    int lmax = g >> 8;
    if (lmax > SEQL - 1) lmax = SEQL - 1;
    float env = 0.0f;
    const float inv = 1.0f / (float)NFFT;
    for (int l = lmin; l <= lmax; ++l) {
        int n = g - (l << 8);
        float w = 0.5f * (1.0f - cosf(TWO_PI * (float)n * inv));
        env += w * w;
    }
    g_invenv[t] = 1.0f / (env > 1e-11f ? env : 1.0f);
}

// W -> fragment-major fp16 g_Wp[kchunk][mblock][k16idx][mtile][lane][8].
__global__ void wperm_kernel(const float* __restrict__ W) {
    int i = blockIdx.x * blockDim.x + threadIdx.x;
    if (i >= 16 * NMBLK * A_HALVES) return;
    int q     = i & 7;
    int lane  = (i >> 3) & 31;
    int mtile = (i >> 8) & 7;
    int k16i  = (i >> 11) & 1;
    int rest  = i >> 12;
    int mblock = rest & 7;
    int kchunk = rest >> 3;
    int lr = lane >> 2, lc = lane & 3;
    int k  = kchunk * 32 + k16i * 16 + 2 * lc + (q & 1) + ((q & 4) ? 8 : 0);
    int mp = mblock * 128 + mtile * 16 + lr + ((q & 2) ? 8 : 0);
    int tile = mp >> 4, w = mp & 15;
    int bin = tile * 8 + (w & 7);                 // < 512 always (NMBLK=8)
    int o = (w < 8) ? bin : (FBINS + bin);
    g_Wp[i] = __float2half_rn(W[(size_t)o * DIM + k]);
}

// x -> fragment-major fp16 g_xB[b][kchunk][lblock][k16idx][ltile][lane][4].
__global__ void xpermute_kernel(const float* __restrict__ x) {
    int j = blockIdx.x * blockDim.x + threadIdx.x;   // 4-half unit index
    if (j >= BATCH * DIM * SEQL / 4) return;
    int lane  = j & 31;
    int ltile = (j >> 5) & 31;
    int k16i  = (j >> 10) & 1;
    int lblock = (j >> 11) & 15;
    int kchunk = (j >> 15) & 15;
    int b = j >> 19;
    int lr = lane >> 2, lc = lane & 3;
    int l = lblock * 256 + ltile * 8 + lr;
    int kb = kchunk * 32 + k16i * 16 + 2 * lc;
    const float* xb = x + (size_t)b * DIM * SEQL + l;
    __half2 h01 = make_half2(__float2half_rn(xb[(size_t)kb * SEQL]),
                             __float2half_rn(xb[(size_t)(kb + 1) * SEQL]));
    __half2 h23 = make_half2(__float2half_rn(xb[(size_t)(kb + 8) * SEQL]),
                             __float2half_rn(xb[(size_t)(kb + 9) * SEQL]));
    uint2 u;
    u.x = *(uint32_t*)&h01;
    u.y = *(uint32_t*)&h23;
    ((uint2*)g_xB)[j] = u;
}

// Nyquist bin (512): plain fp32 dot products, fused spectrum.
__global__ __launch_bounds__(256)
void nyq_kernel(const float* __restrict__ x, const float* __restrict__ W,
                const float* __restrict__ bias) {
    __shared__ float wm[DIM], wp[DIM];
    int tid = threadIdx.x;
    for (int k = tid; k < DIM; k += 256) {
        wm[k] = W[(size_t)512 * DIM + k];
        wp[k] = W[(size_t)1025 * DIM + k];
    }
    __syncthreads();
    int n = blockIdx.x * 256 + tid;
    int b = n >> 12, l = n & (SEQL - 1);
    const float* xb = x + (size_t)b * DIM * SEQL + l;
    float am = 0.0f, ap = 0.0f;
#pragma unroll 8
    for (int k = 0; k < DIM; k++) {
        float xv = xb[(size_t)k * SEQL];
        am += wm[k] * xv;
        ap += wp[k] * xv;
    }
    float mag = fminf(__expf(am + bias[512]), 100.0f);
    float s, c;
    __sincosf(ap + bias[1025], &s, &c);
    g_specT[(size_t)n * KTOT + 512]      = mag * c;
    g_specT[(size_t)n * KTOT + KR + 512] = mag * s;
}

// ---------------------------------------------------------------------------
// GEMM1 (FP16 m16n8k16 mma, fp32 accum, cp.async double-buffered,
// fragment-major operands, fused spectrum epilogue): bins 0..511.
// ---------------------------------------------------------------------------
__global__ __launch_bounds__(NTHR, 1)
void gemm1_mma(const float* __restrict__ bias) {
    extern __shared__ float sm[];
    const uint32_t smem_u32 = (uint32_t)__cvta_generic_to_shared(sm);

    const int mblock = blockIdx.x;
    const int n0 = blockIdx.y * BN;
    const int bidx = n0 >> 12;
    const int lblock = (n0 & (SEQL - 1)) >> 8;

    const int tid = threadIdx.x;
    const int wid = tid >> 5, lane = tid & 31;
    const int wn = (wid >> 1) * 32;
    const int lr = lane >> 2, lc = lane & 3;

    float acc[4][4][4];
#pragma unroll
    for (int i = 0; i < 4; i++)
#pragma unroll
        for (int j = 0; j < 4; j++)
#pragma unroll
            for (int q = 0; q < 4; q++) acc[i][j][q] = 0.0f;

    const int T = DIM / BK;   // 16 kchunks

    auto load_stage = [&](int s) {
        const uint32_t a_base = smem_u32 + (s & 1) * STAGE_BYTES;
        const uint32_t b_base = a_base + A_BYTES;
        const __half* asrc = g_Wp + ((size_t)s * NMBLK + mblock) * A_HALVES;
        const __half* bsrc = g_xB + ((size_t)bidx * 16 * 16 + (size_t)s * 16 + lblock) * B_HALVES;
        CP_ASYNC_CG(a_base + tid * 16, asrc + tid * 8);
#pragma unroll
        for (int i = 0; i < 2; i++) {
            int ch = tid + NTHR * i;
            CP_ASYNC_CG(b_base + ch * 16, bsrc + ch * 8);
        }
        CP_COMMIT();
    };

    const int a_off = (wid & 1) * 1024 + lane * 8;   // halves
    const int b_off = (wid >> 1) * 512 + lane * 4;   // halves

    load_stage(0);
    for (int s = 0; s < T; s++) {
        if (s + 1 < T) { load_stage(s + 1); CP_WAIT1(); } else { CP_WAIT0(); }
        __syncthreads();
        const __half* As = (const __half*)((const char*)sm + (s & 1) * STAGE_BYTES);
        const __half* Bs = As + A_HALVES;
#pragma unroll
        for (int k16i = 0; k16i < 2; k16i++) {
            const __half* Ak = As + k16i * 2048 + a_off;
            const __half* Bk = Bs + k16i * 4096 + b_off;
            uint32_t af[4][4], bf[4][2];
#pragma unroll
            for (int im = 0; im < 4; im++) {
                uint4 v = *(const uint4*)(Ak + im * 256);
                af[im][0] = v.x; af[im][1] = v.y; af[im][2] = v.z; af[im][3] = v.w;
            }
#pragma unroll
            for (int jn = 0; jn < 4; jn++) {
                uint2 v = *(const uint2*)(Bk + jn * 128);
                bf[jn][0] = v.x; bf[jn][1] = v.y;
            }
#pragma unroll
            for (int im = 0; im < 4; im++)
#pragma unroll
                for (int jn = 0; jn < 4; jn++)
                    mma_f16(acc[im][jn], af[im], bf[jn]);
        }
        __syncthreads();
    }

    // ---- Fused spectrum epilogue, transposed to spec_T[m][k] ----
    const int TS = 136;
    float* Tt = sm;                        // 128 x 136 floats
    const int bin0 = mblock * 64;

    for (int h = 0; h < 2; h++) {
        if ((wid >> 3) == h) {
            int cbase = wn & 127;
#pragma unroll
            for (int im = 0; im < 4; im++) {
                int bin_l = ((wid & 1) * 4 + im) * 8 + lr;   // 0..63
                int bin = bin0 + bin_l;
                float bmag = bias[bin];
                float bph  = bias[FBINS + bin];
#pragma unroll
                for (int jn = 0; jn < 4; jn++) {
                    int c_l = cbase + jn * 8 + 2 * lc;
                    float m0v = fminf(__expf(acc[im][jn][0] + bmag), 100.0f);
                    float m1v = fminf(__expf(acc[im][jn][1] + bmag), 100.0f);
                    float s0, c0, s1, c1;
                    __sincosf(acc[im][jn][2] + bph, &s0, &c0);
                    __sincosf(acc[im][jn][3] + bph, &s1, &c1);
                    Tt[c_l * TS + bin_l]            = m0v * c0;
                    Tt[(c_l + 1) * TS + bin_l]      = m1v * c1;
                    Tt[c_l * TS + 64 + bin_l]       = m0v * s0;
                    Tt[(c_l + 1) * TS + 64 + bin_l] = m1v * s1;
                }
            }
        }
        __syncthreads();
        for (int sidx = wid; sidx < 256; sidx += 16) {
            int c_l = sidx >> 1, part = sidx & 1;
            int m_glob = n0 + h * 128 + c_l;
            float* dst = g_specT + (size_t)m_glob * KTOT + (part ? (KR + bin0) : bin0);
            const float* src = Tt + c_l * TS + part * 64;
            dst[lane]      = src[lane];
            dst[lane + 32] = src[lane + 32];
        }
        __syncthreads();
    }
}

// ---------------------------------------------------------------------------
// Fused iFFT + window + overlap-add, dual-frame: 512 threads = two 256-thread
// groups; group g computes frame l0+g per iteration (radix-4 Stockham, named
// barriers per group), 6-slot smem ring, then both hops l0-2 / l0-1 emit.
//   Ring-lifetime proof: emits need frames l0-4..l0+1 = 6 consecutive ints =
//   distinct mod 6; next iteration overwrites slots (l0+2)%6=(l0-4)%6 and
//   (l0+3)%6=(l0-3)%6 only after the trailing __syncthreads.
// ---------------------------------------------------------------------------
__device__ __forceinline__ float2 cmul(float2 x, float2 w) {
    return make_float2(x.x * w.x - x.y * w.y, x.x * w.y + x.y * w.x);
}

__global__ __launch_bounds__(512)
void ifft_ola_kernel(float* __restrict__ out) {
    extern __shared__ float smd[];
    float2* bufs = (float2*)smd;              // 2 groups x 2048 float2 (32KB)
    float* ring = smd + 8192;                 // 6 x 1024 floats (24KB)
    const int blk = blockIdx.x;
    const int b = blk / (SEQL / HOPB);
    const int h0 = (blk % (SEQL / HOPB)) * HOPB;
    const int tid = threadIdx.x;
    const int grp = tid >> 8;                 // 0 or 1 (warp-aligned)
    const int t = tid & 255;
    const int barid = grp + 1;

    float2* bufA = bufs + grp * 2048;
    float2* bufB = bufA + 1024;

    for (int j = 0; j < (HOPB + 4) / 2; ++j) {       // 18 iterations
        const int l = h0 - 2 + 2 * j + grp;
        const int slot = ((l % 6) + 6) % 6;
        float* rs = ring + slot * 1024;

        if (l >= 0 && l < SEQL) {                    // group-uniform branch
            const float* src = g_specT + ((size_t)b * SEQL + l) * KTOT;
            // Load + Hermitian extension
#pragma unroll
            for (int h2 = 0; h2 < 2; h2++) {
                int jj = t + h2 * 256;               // 0..511
                float re = src[jj];
                float im = src[KR + jj];
                bufA[jj] = make_float2(re, im);
                if (jj > 0) bufA[1024 - jj] = make_float2(re, -im);
            }
            if (t == 0)
                bufA[512] = make_float2(src[512], src[KR + 512]);
            BAR_GRP(barid);

            float2* X = bufA;
            float2* Y = bufB;
#pragma unroll
            for (int st = 0; st < 5; st++) {
                const int s = 1 << (2 * st);
                const int i = t;
                float2 a = X[i];
                float2 bb = X[i + 256];
                float2 c = X[i + 512];
                float2 d = X[i + 768];
                float2 t0 = make_float2(a.x + c.x, a.y + c.y);
                float2 t1 = make_float2(a.x - c.x, a.y - c.y);
                float2 t2 = make_float2(bb.x + d.x, bb.y + d.y);
                float2 t3 = make_float2(-(bb.y - d.y), bb.x - d.x);   // +i*(b-d)
                int ps = i & ~(s - 1);
                int o  = (i & (s - 1)) + ((i >> (2 * st)) << (2 * st + 2));
                float2 F0 = make_float2(t0.x + t2.x, t0.y + t2.y);
                float2 F1 = make_float2(t1.x + t3.x, t1.y + t3.y);
                float2 F2 = make_float2(t0.x - t2.x, t0.y - t2.y);
                float2 F3 = make_float2(t1.x - t3.x, t1.y - t3.y);
                Y[o]         = F0;
                Y[o + s]     = cmul(F1, g_tw[ps]);
                Y[o + 2 * s] = cmul(F2, g_tw[2 * ps]);
                Y[o + 3 * s] = cmul(F3, g_tw[3 * ps]);
                BAR_GRP(barid);
                float2* tmp = X; X = Y; Y = tmp;
            }
            // Window + store into ring slot
#pragma unroll
            for (int h2 = 0; h2 < 4; h2++) {
                int n = t + h2 * 256;
                rs[n] = X[n].x * g_winS[n];
            }
        } else {
#pragma unroll
            for (int h2 = 0; h2 < 4; h2++)
                rs[t + h2 * 256] = 0.0f;
        }
        __syncthreads();                     // both ring slots visible

        // group 0 emits hop l0-2, group 1 emits hop l0-1
        const int h = h0 - 4 + 2 * j + grp;
        if (h >= h0 && h < h0 + HOPB) {
            int tt = h * HOP + t;
            float acc = ring[((((h - 1) % 6) + 6) % 6) * 1024 + 640 + t]
                      + ring[((((h    ) % 6) + 6) % 6) * 1024 + 384 + t]
                      + ring[((((h + 1) % 6) + 6) % 6) * 1024 + 128 + t];
            if (t < 128)
                acc += ring[((((h - 2) % 6) + 6) % 6) * 1024 + 896 + t];
            else
                acc += ring[((((h + 2) % 6) + 6) % 6) * 1024 + (t - 128)];
            out[(size_t)b * OUTPER + tt] = acc * g_invenv[tt];
        }
        __syncthreads();                     // emits done before slot reuse
    }
}

// ---------------------------------------------------------------------------
// Launch
// ---------------------------------------------------------------------------
extern "C" void kernel_launch(void* const* d_in, const int* in_sizes, int n_in,
                              void* d_out, int out_size) {
    const float* x    = (const float*)d_in[0];   // (16, 512, 4096)
    const float* W    = (const float*)d_in[1];   // (1026, 512)
    const float* bias = (const float*)d_in[2];   // (1026,)
    float* out = (float*)d_out;                  // (16, 1048576)

    cudaFuncSetAttribute(gemm1_mma, cudaFuncAttributeMaxDynamicSharedMemorySize, SMEM_BYTES);
    cudaFuncSetAttribute(ifft_ola_kernel, cudaFuncAttributeMaxDynamicSharedMemorySize, OLA_SMEM);

    gen_tables_kernel<<<4, 256>>>();
    gen_invenv_kernel<<<OUTPER / 256, 256>>>();
    wperm_kernel<<<(16 * NMBLK * A_HALVES + 255) / 256, 256>>>(W);
    xpermute_kernel<<<(BATCH * DIM * SEQL / 4 + 255) / 256, 256>>>(x);

    nyq_kernel<<<NCOL / 256, 256>>>(x, W, bias);

    gemm1_mma<<<dim3(NMBLK, NCOL / BN), NTHR, SMEM_BYTES>>>(bias);

    ifft_ola_kernel<<<BATCH * (SEQL / HOPB), 512, OLA_SMEM>>>(out);
}

// round 16
// speedup vs baseline: 1.0392x; 1.0392x over previous
#include <cuda_runtime.h>
#include <cuda_fp16.h>
#include <cstdint>
#include <math.h>

// Problem constants
#define BATCH   16
#define DIM     512
#define SEQL    4096
#define NFFT    1024
#define HOP     256
#define FBINS   513          // NFFT/2 + 1
#define NCOL    65536        // BATCH * SEQL
#define OUTPER  1048576      // SEQL * HOP
#define PAD     384          // (NFFT - HOP)/2
#define TWO_PI  6.283185307179586476925286766559f

// spec_T K layout: [Re: 0..512][pad][Im: 544..1056][pad]
#define KR      544
#define KTOT    1088

// GEMM1 covers bins 0..511 (8 mblocks); bin 512 handled by nyq_kernel.
#define NMBLK   8

// GEMM1 tiling: block 128x256, 512 threads, warp tile 64x32 (2x8 grid), fp16 mma
#define BM 128
#define BN 256
#define BK 32
#define NTHR 512
#define A_HALVES 4096
#define B_HALVES 8192
#define A_BYTES  (A_HALVES * 2)  // 8192
#define B_BYTES  (B_HALVES * 2)  // 16384
#define STAGE_BYTES (A_BYTES + B_BYTES)   // 24576
#define NSTAGE 4
#define SMEM_BYTES (NSTAGE * STAGE_BYTES) // 98304 >= Tt (69632)

// Fused iFFT+OLA: hops per block
#define HOPB 32

// ---------------------------------------------------------------------------
// Scratch (static device globals)
// ---------------------------------------------------------------------------
__device__ float  g_specT[(size_t)NCOL * KTOT];       // spec m-major [m][k], fp32
__device__ __half g_xB[(size_t)BATCH * DIM * SEQL];   // x, fragment-major fp16
__device__ __half g_Wp[(size_t)16 * NMBLK * A_HALVES];// W, fragment-major fp16
__device__ float2 g_tw[1024];                         // exp(+2*pi*i*a/1024)
__device__ float  g_winS[NFFT];                       // hann[n] / 1024
__device__ float  g_invenv[OUTPER];                   // 1 / window-square envelope

__device__ __forceinline__ void mma_f16(float c[4], const uint32_t a[4], const uint32_t b[2]) {
    asm volatile(
        "mma.sync.aligned.m16n8k16.row.col.f32.f16.f16.f32 "
        "{%0,%1,%2,%3}, {%4,%5,%6,%7}, {%8,%9}, {%0,%1,%2,%3};\n"
        : "+f"(c[0]), "+f"(c[1]), "+f"(c[2]), "+f"(c[3])
        : "r"(a[0]), "r"(a[1]), "r"(a[2]), "r"(a[3]), "r"(b[0]), "r"(b[1]));
}

#define CP_ASYNC_CG(dst_u32, src_ptr) \
    asm volatile("cp.async.cg.shared.global [%0], [%1], 16;\n" \
                 :: "r"(dst_u32), "l"(src_ptr))
#define CP_COMMIT() asm volatile("cp.async.commit_group;\n")
#define CP_WAIT2()  asm volatile("cp.async.wait_group 2;\n")

// ---------------------------------------------------------------------------
// Prep kernels
// ---------------------------------------------------------------------------
__global__ void gen_tables_kernel() {
    int i = blockIdx.x * blockDim.x + threadIdx.x;
    if (i < 1024) {
        float s, c;
        sincosf(TWO_PI * (float)i * (1.0f / 1024.0f), &s, &c);
        g_tw[i] = make_float2(c, s);
        float w = 0.5f * (1.0f - c);      // hann[i]
        g_winS[i] = w * (1.0f / 1024.0f);
    }
}

// Precompute 1/env(t): env = sum over valid frames of hann^2 (batch-independent).
__global__ void gen_invenv_kernel() {
    int t = blockIdx.x * blockDim.x + threadIdx.x;
    if (t >= OUTPER) return;
    int g = t + PAD;
    int lmin = (g - (NFFT - 1) + (HOP - 1)) >> 8;
    if (lmin < 0) lmin = 0;
    int lmax = g >> 8;
    if (lmax > SEQL - 1) lmax = SEQL - 1;
    float env = 0.0f;
    const float inv = 1.0f / (float)NFFT;
    for (int l = lmin; l <= lmax; ++l) {
        int n = g - (l << 8);
        float w = 0.5f * (1.0f - cosf(TWO_PI * (float)n * inv));
        env += w * w;
    }
    g_invenv[t] = 1.0f / (env > 1e-11f ? env : 1.0f);
}

// W -> fragment-major fp16 g_Wp[kchunk][mblock][k16idx][mtile][lane][8].
__global__ void wperm_kernel(const float* __restrict__ W) {
    int i = blockIdx.x * blockDim.x + threadIdx.x;
    if (i >= 16 * NMBLK * A_HALVES) return;
    int q     = i & 7;
    int lane  = (i >> 3) & 31;
    int mtile = (i >> 8) & 7;
    int k16i  = (i >> 11) & 1;
    int rest  = i >> 12;
    int mblock = rest & 7;
    int kchunk = rest >> 3;
    int lr = lane >> 2, lc = lane & 3;
    int k  = kchunk * 32 + k16i * 16 + 2 * lc + (q & 1) + ((q & 4) ? 8 : 0);
    int mp = mblock * 128 + mtile * 16 + lr + ((q & 2) ? 8 : 0);
    int tile = mp >> 4, w = mp & 15;
    int bin = tile * 8 + (w & 7);                 // < 512 always (NMBLK=8)
    int o = (w < 8) ? bin : (FBINS + bin);
    g_Wp[i] = __float2half_rn(W[(size_t)o * DIM + k]);
}

// x -> fragment-major fp16 g_xB[b][kchunk][lblock][k16idx][ltile][lane][4].
__global__ void xpermute_kernel(const float* __restrict__ x) {
    int j = blockIdx.x * blockDim.x + threadIdx.x;   // 4-half unit index
    if (j >= BATCH * DIM * SEQL / 4) return;
    int lane  = j & 31;
    int ltile = (j >> 5) & 31;
    int k16i  = (j >> 10) & 1;
    int lblock = (j >> 11) & 15;
    int kchunk = (j >> 15) & 15;
    int b = j >> 19;
    int lr = lane >> 2, lc = lane & 3;
    int l = lblock * 256 + ltile * 8 + lr;
    int kb = kchunk * 32 + k16i * 16 + 2 * lc;
    const float* xb = x + (size_t)b * DIM * SEQL + l;
    __half2 h01 = make_half2(__float2half_rn(xb[(size_t)kb * SEQL]),
                             __float2half_rn(xb[(size_t)(kb + 1) * SEQL]));
    __half2 h23 = make_half2(__float2half_rn(xb[(size_t)(kb + 8) * SEQL]),
                             __float2half_rn(xb[(size_t)(kb + 9) * SEQL]));
    uint2 u;
    u.x = *(uint32_t*)&h01;
    u.y = *(uint32_t*)&h23;
    ((uint2*)g_xB)[j] = u;
}

// Nyquist bin (512): plain fp32 dot products, fused spectrum.
__global__ __launch_bounds__(256)
void nyq_kernel(const float* __restrict__ x, const float* __restrict__ W,
                const float* __restrict__ bias) {
    __shared__ float wm[DIM], wp[DIM];
    int tid = threadIdx.x;
    for (int k = tid; k < DIM; k += 256) {
        wm[k] = W[(size_t)512 * DIM + k];
        wp[k] = W[(size_t)1025 * DIM + k];
    }
    __syncthreads();
    int n = blockIdx.x * 256 + tid;
    int b = n >> 12, l = n & (SEQL - 1);
    const float* xb = x + (size_t)b * DIM * SEQL + l;
    float am = 0.0f, ap = 0.0f;
#pragma unroll 8
    for (int k = 0; k < DIM; k++) {
        float xv = xb[(size_t)k * SEQL];
        am += wm[k] * xv;
        ap += wp[k] * xv;
    }
    float mag = fminf(__expf(am + bias[512]), 100.0f);
    float s, c;
    __sincosf(ap + bias[1025], &s, &c);
    g_specT[(size_t)n * KTOT + 512]      = mag * c;
    g_specT[(size_t)n * KTOT + KR + 512] = mag * s;
}

// ---------------------------------------------------------------------------
// GEMM1 (FP16 m16n8k16 mma, fp32 accum, cp.async 4-buffer 3-deep pipeline,
// fragment-major operands, fused spectrum epilogue): bins 0..511.
// Commit-every-iteration keeps outstanding-group count uniform so a constant
// wait_group 2 always guarantees stage s is resident.
// ---------------------------------------------------------------------------
__global__ __launch_bounds__(NTHR, 1)
void gemm1_mma(const float* __restrict__ bias) {
    extern __shared__ float sm[];
    const uint32_t smem_u32 = (uint32_t)__cvta_generic_to_shared(sm);

    const int mblock = blockIdx.x;
    const int n0 = blockIdx.y * BN;
    const int bidx = n0 >> 12;
    const int lblock = (n0 & (SEQL - 1)) >> 8;

    const int tid = threadIdx.x;
    const int wid = tid >> 5, lane = tid & 31;
    const int wn = (wid >> 1) * 32;
    const int lr = lane >> 2, lc = lane & 3;

    float acc[4][4][4];
#pragma unroll
    for (int i = 0; i < 4; i++)
#pragma unroll
        for (int j = 0; j < 4; j++)
#pragma unroll
            for (int q = 0; q < 4; q++) acc[i][j][q] = 0.0f;

    const int T = DIM / BK;   // 16 kchunks

    auto issue_stage = [&](int s) {
        const uint32_t a_base = smem_u32 + (s & (NSTAGE - 1)) * STAGE_BYTES;
        const uint32_t b_base = a_base + A_BYTES;
        const __half* asrc = g_Wp + ((size_t)s * NMBLK + mblock) * A_HALVES;
        const __half* bsrc = g_xB + ((size_t)bidx * 16 * 16 + (size_t)s * 16 + lblock) * B_HALVES;
        CP_ASYNC_CG(a_base + tid * 16, asrc + tid * 8);
#pragma unroll
        for (int i = 0; i < 2; i++) {
            int ch = tid + NTHR * i;
            CP_ASYNC_CG(b_base + ch * 16, bsrc + ch * 8);
        }
    };

    const int a_off = (wid & 1) * 1024 + lane * 8;   // halves
    const int b_off = (wid >> 1) * 512 + lane * 4;   // halves

    // Prologue: stages 0..2 in flight
#pragma unroll
    for (int p = 0; p < 3; p++) { issue_stage(p); CP_COMMIT(); }

    for (int s = 0; s < T; s++) {
        CP_WAIT2();                 // commits 0..s+2 exist; newest 2 may lag -> s done
        __syncthreads();
        const __half* As = (const __half*)((const char*)sm + (s & (NSTAGE - 1)) * STAGE_BYTES);
        const __half* Bs = As + A_HALVES;
#pragma unroll
        for (int k16i = 0; k16i < 2; k16i++) {
            const __half* Ak = As + k16i * 2048 + a_off;
            const __half* Bk = Bs + k16i * 4096 + b_off;
            uint32_t af[4][4], bf[4][2];
#pragma unroll
            for (int im = 0; im < 4; im++) {
                uint4 v = *(const uint4*)(Ak + im * 256);
                af[im][0] = v.x; af[im][1] = v.y; af[im][2] = v.z; af[im][3] = v.w;
            }
#pragma unroll
            for (int jn = 0; jn < 4; jn++) {
                uint2 v = *(const uint2*)(Bk + jn * 128);
                bf[jn][0] = v.x; bf[jn][1] = v.y;
            }
#pragma unroll
            for (int im = 0; im < 4; im++)
#pragma unroll
                for (int jn = 0; jn < 4; jn++)
                    mma_f16(acc[im][jn], af[im], bf[jn]);
        }
        __syncthreads();            // stage s dead before its buffer is reused
        if (s + 3 < T) issue_stage(s + 3);
        CP_COMMIT();                // commit even when empty (uniform count)
    }

    // ---- Fused spectrum epilogue, transposed to spec_T[m][k] ----
    const int TS = 136;
    float* Tt = sm;                        // 128 x 136 floats (69.6KB < 96KB)
    const int bin0 = mblock * 64;

    for (int h = 0; h < 2; h++) {
        if ((wid >> 3) == h) {
            int cbase = wn & 127;
#pragma unroll
            for (int im = 0; im < 4; im++) {
                int bin_l = ((wid & 1) * 4 + im) * 8 + lr;   // 0..63
                int bin = bin0 + bin_l;
                float bmag = bias[bin];
                float bph  = bias[FBINS + bin];
#pragma unroll
                for (int jn = 0; jn < 4; jn++) {
                    int c_l = cbase + jn * 8 + 2 * lc;
                    float m0v = fminf(__expf(acc[im][jn][0] + bmag), 100.0f);
                    float m1v = fminf(__expf(acc[im][jn][1] + bmag), 100.0f);
                    float s0, c0, s1, c1;
                    __sincosf(acc[im][jn][2] + bph, &s0, &c0);
                    __sincosf(acc[im][jn][3] + bph, &s1, &c1);
                    Tt[c_l * TS + bin_l]            = m0v * c0;
                    Tt[(c_l + 1) * TS + bin_l]      = m1v * c1;
                    Tt[c_l * TS + 64 + bin_l]       = m0v * s0;
                    Tt[(c_l + 1) * TS + 64 + bin_l] = m1v * s1;
                }
            }
        }
        __syncthreads();
        for (int sidx = wid; sidx < 256; sidx += 16) {
            int c_l = sidx >> 1, part = sidx & 1;
            int m_glob = n0 + h * 128 + c_l;
            float* dst = g_specT + (size_t)m_glob * KTOT + (part ? (KR + bin0) : bin0);
            const float* src = Tt + c_l * TS + part * 64;
            dst[lane]      = src[lane];
            dst[lane + 32] = src[lane + 32];
        }
        __syncthreads();
    }
}

// ---------------------------------------------------------------------------
// Fused iFFT + window + overlap-add (radix-4 Stockham, 5-slot ring).
// (R13 version — measured-best; the dual-frame split regressed.)
// ---------------------------------------------------------------------------
__device__ __forceinline__ float2 cmul(float2 x, float2 w) {
    return make_float2(x.x * w.x - x.y * w.y, x.x * w.y + x.y * w.x);
}

__global__ __launch_bounds__(256)
void ifft_ola_kernel(float* __restrict__ out) {
    __shared__ float2 bufA[1024];
    __shared__ float2 bufB[1024];
    __shared__ float ring[5][1024];
    const int blk = blockIdx.x;
    const int b = blk / (SEQL / HOPB);
    const int h0 = (blk % (SEQL / HOPB)) * HOPB;
    const int tid = threadIdx.x;

    for (int l = h0 - 2; l <= h0 + HOPB + 1; ++l) {
        const int slot = (l + 10) % 5;
        if (l >= 0 && l < SEQL) {
            const float* src = g_specT + ((size_t)b * SEQL + l) * KTOT;
#pragma unroll
            for (int h2 = 0; h2 < 2; h2++) {
                int j = tid + h2 * 256;               // 0..511
                float re = src[j];
                float im = src[KR + j];
                bufA[j] = make_float2(re, im);
                if (j > 0) bufA[1024 - j] = make_float2(re, -im);
            }
            if (tid == 0)
                bufA[512] = make_float2(src[512], src[KR + 512]);
            __syncthreads();

            float2* X = bufA;
            float2* Y = bufB;
#pragma unroll
            for (int st = 0; st < 5; st++) {
                const int s = 1 << (2 * st);
                const int i = tid;
                float2 a = X[i];
                float2 bb = X[i + 256];
                float2 c = X[i + 512];
                float2 d = X[i + 768];
                float2 t0 = make_float2(a.x + c.x, a.y + c.y);
                float2 t1 = make_float2(a.x - c.x, a.y - c.y);
                float2 t2 = make_float2(bb.x + d.x, bb.y + d.y);
                float2 t3 = make_float2(-(bb.y - d.y), bb.x - d.x);   // +i*(b-d)
                int ps = i & ~(s - 1);
                int o  = (i & (s - 1)) + ((i >> (2 * st)) << (2 * st + 2));
                float2 F0 = make_float2(t0.x + t2.x, t0.y + t2.y);
                float2 F1 = make_float2(t1.x + t3.x, t1.y + t3.y);
                float2 F2 = make_float2(t0.x - t2.x, t0.y - t2.y);
                float2 F3 = make_float2(t1.x - t3.x, t1.y - t3.y);
                Y[o]         = F0;
                Y[o + s]     = cmul(F1, g_tw[ps]);
                Y[o + 2 * s] = cmul(F2, g_tw[2 * ps]);
                Y[o + 3 * s] = cmul(F3, g_tw[3 * ps]);
                __syncthreads();
                float2* t = X; X = Y; Y = t;
            }
#pragma unroll
            for (int h2 = 0; h2 < 4; h2++) {
                int n = tid + h2 * 256;
                ring[slot][n] = X[n].x * g_winS[n];
            }
        } else {
#pragma unroll
            for (int h2 = 0; h2 < 4; h2++)
                ring[slot][tid + h2 * 256] = 0.0f;
        }
        __syncthreads();

        const int h = l - 2;                 // hop emittable now
        if (h >= h0 && h < h0 + HOPB) {
            int t = h * HOP + tid;
            float acc = ring[(h - 1 + 10) % 5][640 + tid]
                      + ring[(h     + 10) % 5][384 + tid]
                      + ring[(h + 1 + 10) % 5][128 + tid];
            if (tid < 128)
                acc += ring[(h - 2 + 10) % 5][896 + tid];
            else
                acc += ring[(h + 2 + 10) % 5][tid - 128];
            out[(size_t)b * OUTPER + t] = acc * g_invenv[t];
        }
        __syncthreads();
    }
}

// ---------------------------------------------------------------------------
// Launch
// ---------------------------------------------------------------------------
extern "C" void kernel_launch(void* const* d_in, const int* in_sizes, int n_in,
                              void* d_out, int out_size) {
    const float* x    = (const float*)d_in[0];   // (16, 512, 4096)
    const float* W    = (const float*)d_in[1];   // (1026, 512)
    const float* bias = (const float*)d_in[2];   // (1026,)
    float* out = (float*)d_out;                  // (16, 1048576)

    cudaFuncSetAttribute(gemm1_mma, cudaFuncAttributeMaxDynamicSharedMemorySize, SMEM_BYTES);

    gen_tables_kernel<<<4, 256>>>();
    gen_invenv_kernel<<<OUTPER / 256, 256>>>();
    wperm_kernel<<<(16 * NMBLK * A_HALVES + 255) / 256, 256>>>(W);
    xpermute_kernel<<<(BATCH * DIM * SEQL / 4 + 255) / 256, 256>>>(x);

    nyq_kernel<<<NCOL / 256, 256>>>(x, W, bias);

    gemm1_mma<<<dim3(NMBLK, NCOL / BN), NTHR, SMEM_BYTES>>>(bias);

    ifft_ola_kernel<<<BATCH * (SEQL / HOPB), 256>>>(out);
}